// round 7
// baseline (speedup 1.0000x reference)
#include <cuda_runtime.h>
#include <stdint.h>

// Sort_Latent_Layer: z (B, 1, 8192) fp32. Per row: 512 packets x 16 floats,
// stable-sort packets by packet[0] ascending, gather, write back.
//
// R4 design: one WARP per row, 16 items per lane held in registers.
//  - Bitonic network on i = lane*16 + v:
//      j < 16  -> register-local compare-exchange (30 of 45 stages, no comm)
//      j >= 16 -> __shfl_xor (15 stages), NO smem, NO __syncthreads
//  - Item = (monotone-uint32 key << 32) | index  -> unique, stable tiebreak.
//  - Permutation published to a tiny smem array (u16), then gather goes
//    global->global: 4 consecutive lanes read one 64B-contiguous packet
//    (full sector utilization), writes perfectly coalesced.

#define NPK 512
#define V   16
#define ROWS_PER_CTA 4
#define THREADS (32 * ROWS_PER_CTA)

__device__ __forceinline__ void ce(unsigned long long &x, unsigned long long &y, bool up)
{
    // ensure x<y ordering ascending iff up; items are distinct
    bool sw = (x > y) == up;
    unsigned long long a = sw ? y : x;
    unsigned long long b = sw ? x : y;
    x = a; y = b;
}

__global__ void __launch_bounds__(THREADS, 7)
sort_latent_kernel(const float* __restrict__ z, float* __restrict__ out, int B)
{
    __shared__ uint16_t sperm[ROWS_PER_CTA][NPK];

    const int lane = threadIdx.x & 31;
    const int w    = threadIdx.x >> 5;
    const int row  = blockIdx.x * ROWS_PER_CTA + w;
    if (row >= B) return;                       // whole-warp exit, no CTA barriers used

    const float* __restrict__ zr = z + (long long)row * 8192;

    // ---- load keys (strided, 32B sectors land in L2 for the later gather) ----
    unsigned long long it[V];
    #pragma unroll
    for (int v = 0; v < V; ++v) {
        int i = lane * V + v;                   // blocked item assignment
        uint32_t kb = __float_as_uint(zr[i * 16]);
        kb = (kb & 0x80000000u) ? ~kb : (kb | 0x80000000u);  // monotone float->uint
        it[v] = ((unsigned long long)kb << 32) | (unsigned)i;
    }

    // ---- bitonic phase A: k = 2..16, all register-local (j < 16) ----
    #pragma unroll
    for (int k = 2; k <= V; k <<= 1) {
        #pragma unroll
        for (int j = k >> 1; j >= 1; j >>= 1) {
            #pragma unroll
            for (int v = 0; v < V; ++v) {
                if ((v & j) == 0) {
                    int i = lane * V + v;
                    bool up = ((i & k) == 0);   // compile-time for k<=8, lane-bit for k=16
                    ce(it[v], it[v | j], up);
                }
            }
        }
    }

    // ---- bitonic phase B: k = 32..512 ----
    #pragma unroll
    for (int k = 32; k <= 512; k <<= 1) {
        const bool up = ((lane & (k >> 4)) == 0);       // k=512 -> always up
        // cross-lane stages: j = k/2 .. 16  (shfl only)
        #pragma unroll
        for (int j = k >> 1; j >= V; j >>= 1) {
            const int  dl      = j >> 4;                 // lane xor distance
            const bool keepmin = (((lane & dl) == 0) == up);
            #pragma unroll
            for (int v = 0; v < V; ++v) {
                unsigned long long other = __shfl_xor_sync(0xFFFFFFFFu, it[v], dl);
                if ((other < it[v]) == keepmin) it[v] = other;
            }
        }
        // register-local tail: j = 8..1, direction uniform per lane
        #pragma unroll
        for (int j = V >> 1; j >= 1; j >>= 1) {
            #pragma unroll
            for (int v = 0; v < V; ++v)
                if ((v & j) == 0) ce(it[v], it[v | j], up);
        }
    }

    // ---- publish permutation (dest packet d = lane*16+v, src = idx bits) ----
    uint16_t* p = sperm[w];
    #pragma unroll
    for (int v = 0; v < V; ++v)
        p[lane * V + v] = (uint16_t)(it[v] & 0x1FFu);
    __syncwarp();

    // ---- gather: global -> global ----
    // f enumerates row float4s with lanes consecutive -> coalesced writes;
    // 4 consecutive lanes read one contiguous 64B packet chunk -> full sectors.
    const float4* __restrict__ in4  = (const float4*)zr;
    float4* __restrict__       out4 = (float4*)(out + (long long)row * 8192);
    #pragma unroll 8
    for (int jj = 0; jj < 64; ++jj) {
        int f   = jj * 32 + lane;
        int src = p[f >> 2];
        out4[f] = in4[src * 4 + (f & 3)];
    }
}

extern "C" void kernel_launch(void* const* d_in, const int* in_sizes, int n_in,
                              void* d_out, int out_size)
{
    const float* z = (const float*)d_in[0];
    float* out     = (float*)d_out;
    const int D = 8192;                  // 512 packets * 16 floats
    int B = in_sizes[0] / D;             // 4096
    int grid = (B + ROWS_PER_CTA - 1) / ROWS_PER_CTA;
    sort_latent_kernel<<<grid, THREADS>>>(z, out, B);
}

// round 8
// speedup vs baseline: 1.0422x; 1.0422x over previous
#include <cuda_runtime.h>
#include <stdint.h>

// Sort_Latent_Layer: z (B, 1, 8192) fp32. Per row: 512 packets x 16 floats,
// stable-sort packets by packet[0] ascending, gather, write back.
//
// R7: warp-per-row register/shfl bitonic sort (validated in R4) + TMA bulk
// staging of the row into smem so the gather never touches L2/DRAM twice.
//   warp timeline: issue cp.async.bulk (32KB row -> smem)
//                  || LDG keys + full bitonic sort (hidden under the copy)
//                  -> mbarrier wait -> gather from smem -> coalesced STG.128
// DRAM traffic = read row once + write row once = hard floor (256 MB total).

#define NPK 512
#define V   16
#define WARPS_PER_CTA 2
#define THREADS (32 * WARPS_PER_CTA)

#define ROW_BYTES   32768
#define PERM_BYTES  1024
#define SLOT_BYTES  (ROW_BYTES + PERM_BYTES + 64)   // data | perm | mbar+pad

__device__ __forceinline__ uint32_t smem_u32(const void* p)
{
    uint32_t a;
    asm("{ .reg .u64 t; cvta.to.shared.u64 t, %1; cvt.u32.u64 %0, t; }"
        : "=r"(a) : "l"(p));
    return a;
}

__device__ __forceinline__ void ce(unsigned long long &x, unsigned long long &y, bool up)
{
    bool sw = (x > y) == up;          // items are distinct
    unsigned long long a = sw ? y : x;
    unsigned long long b = sw ? x : y;
    x = a; y = b;
}

__device__ __forceinline__ void mbar_wait(uint32_t mbar)
{
    uint32_t done;
    asm volatile(
        "{\n\t.reg .pred p;\n\t"
        "mbarrier.try_wait.parity.acquire.cta.shared::cta.b64 p, [%1], 0;\n\t"
        "selp.b32 %0, 1, 0, p;\n\t}"
        : "=r"(done) : "r"(mbar) : "memory");
    if (!done) {
        asm volatile(
            "{\n\t.reg .pred P1;\n\t"
            "W_%=:\n\t"
            "mbarrier.try_wait.parity.acquire.cta.shared::cta.b64 P1, [%0], 0, 0x989680;\n\t"
            "@P1 bra.uni D_%=;\n\t"
            "bra.uni W_%=;\n\t"
            "D_%=:\n\t}"
            :: "r"(mbar) : "memory");
    }
}

__global__ void __launch_bounds__(THREADS, 3)
sort_latent_kernel(const float* __restrict__ z, float* __restrict__ out, int B)
{
    extern __shared__ char smem[];

    const int lane = threadIdx.x & 31;
    const int w    = threadIdx.x >> 5;
    const int row  = blockIdx.x * WARPS_PER_CTA + w;
    if (row >= B) return;                       // whole-warp exit; no CTA barriers

    char* slot = smem + w * SLOT_BYTES;
    float4*   sdata = (float4*)slot;
    uint16_t* perm  = (uint16_t*)(slot + ROW_BYTES);
    uint32_t  mbar  = smem_u32(slot + ROW_BYTES + PERM_BYTES);

    const float* __restrict__ zr = z + (long long)row * 8192;

    // ---- kick off bulk copy: row -> smem (async, hw-pipelined) ----
    if (lane == 0) {
        asm volatile("mbarrier.init.shared.b64 [%0], 1;" :: "r"(mbar) : "memory");
    }
    __syncwarp();
    if (lane == 0) {
        asm volatile("mbarrier.arrive.expect_tx.shared.b64 _, [%0], %1;"
                     :: "r"(mbar), "r"(ROW_BYTES) : "memory");
        asm volatile(
            "cp.async.bulk.shared::cluster.global.mbarrier::complete_tx::bytes "
            "[%0], [%1], %2, [%3];"
            :: "r"(smem_u32(sdata)), "l"(zr), "r"(ROW_BYTES), "r"(mbar)
            : "memory");
    }

    // ---- keys via LDG (overlaps the bulk copy; sectors shared with it in L2) ----
    unsigned long long it[V];
    #pragma unroll
    for (int v = 0; v < V; ++v) {
        int i = lane * V + v;                   // blocked item assignment
        uint32_t kb = __float_as_uint(__ldg(zr + i * 16));
        kb = (kb & 0x80000000u) ? ~kb : (kb | 0x80000000u);   // monotone
        it[v] = ((unsigned long long)kb << 32) | (unsigned)i;
    }

    // ---- bitonic sort, 512 items (register-local + shfl), hidden under TMA ----
    #pragma unroll
    for (int k = 2; k <= V; k <<= 1) {
        #pragma unroll
        for (int j = k >> 1; j >= 1; j >>= 1) {
            #pragma unroll
            for (int v = 0; v < V; ++v) {
                if ((v & j) == 0) {
                    int i = lane * V + v;
                    bool up = ((i & k) == 0);
                    ce(it[v], it[v | j], up);
                }
            }
        }
    }
    #pragma unroll
    for (int k = 32; k <= 512; k <<= 1) {
        const bool up = ((lane & (k >> 4)) == 0);
        #pragma unroll
        for (int j = k >> 1; j >= V; j >>= 1) {
            const int  dl      = j >> 4;
            const bool keepmin = (((lane & dl) == 0) == up);
            #pragma unroll
            for (int v = 0; v < V; ++v) {
                unsigned long long other = __shfl_xor_sync(0xFFFFFFFFu, it[v], dl);
                if ((other < it[v]) == keepmin) it[v] = other;
            }
        }
        #pragma unroll
        for (int j = V >> 1; j >= 1; j >>= 1) {
            #pragma unroll
            for (int v = 0; v < V; ++v)
                if ((v & j) == 0) ce(it[v], it[v | j], up);
        }
    }

    // ---- publish permutation (pairs packed into u32 stores) ----
    uint32_t* perm32 = (uint32_t*)perm;
    #pragma unroll
    for (int v = 0; v < V; v += 2) {
        uint32_t lo = (uint32_t)(it[v]     & 0x1FFu);
        uint32_t hi = (uint32_t)(it[v + 1] & 0x1FFu);
        perm32[(lane * V + v) >> 1] = lo | (hi << 16);
    }
    __syncwarp();

    // ---- wait for the staged row, gather from smem, coalesced write ----
    mbar_wait(mbar);

    float4* __restrict__ out4 = (float4*)(out + (long long)row * 8192);
    #pragma unroll 8
    for (int jj = 0; jj < 64; ++jj) {
        int f   = jj * 32 + lane;
        int src = perm[f >> 2];
        out4[f] = sdata[src * 4 + (f & 3)];
    }
}

extern "C" void kernel_launch(void* const* d_in, const int* in_sizes, int n_in,
                              void* d_out, int out_size)
{
    const float* z = (const float*)d_in[0];
    float* out     = (float*)d_out;
    const int D = 8192;                  // 512 packets * 16 floats
    int B = in_sizes[0] / D;             // 4096

    static int smem_set = 0;
    if (!smem_set) {
        cudaFuncSetAttribute(sort_latent_kernel,
                             cudaFuncAttributeMaxDynamicSharedMemorySize,
                             WARPS_PER_CTA * SLOT_BYTES);
        smem_set = 1;
    }
    int grid = (B + WARPS_PER_CTA - 1) / WARPS_PER_CTA;
    sort_latent_kernel<<<grid, THREADS, WARPS_PER_CTA * SLOT_BYTES>>>(z, out, B);
}

// round 9
// speedup vs baseline: 1.0604x; 1.0174x over previous
#include <cuda_runtime.h>
#include <stdint.h>

// Sort_Latent_Layer: z (B, 1, 8192) fp32. Per row: 512 packets x 16 floats,
// stable-sort packets by packet[0] ascending, gather, write back.
//
// R8: warp-per-row register/shfl bitonic sort (R4) + global->global gather,
// with L2-footprint control instead of smem staging:
//   - persistent grid: exactly 5 CTAs/SM x 4 warps = 20 warps/SM
//     -> in-flight row footprint ~95 MB < 126 MB L2, so key sectors read in
//        phase 1 are still L2-resident for the gather -> DRAM = floor.
//   - __ldlu on gather reads (last use), __stcs on writes (no L2 pollution).
//   - gather batched 8 loads -> 8 stores for MLP.

#define NPK 512
#define V   16
#define WARPS_PER_CTA 4
#define THREADS (32 * WARPS_PER_CTA)
#define CTAS_PER_SM 5

__device__ __forceinline__ void ce(unsigned long long &x, unsigned long long &y, bool up)
{
    bool sw = (x > y) == up;          // items are distinct (idx in low bits)
    unsigned long long a = sw ? y : x;
    unsigned long long b = sw ? x : y;
    x = a; y = b;
}

__global__ void __launch_bounds__(THREADS)
sort_latent_kernel(const float* __restrict__ z, float* __restrict__ out, int B)
{
    __shared__ uint16_t sperm[WARPS_PER_CTA][NPK];

    const int lane = threadIdx.x & 31;
    const int w    = threadIdx.x >> 5;
    const int warps_total = gridDim.x * WARPS_PER_CTA;

    for (int row = blockIdx.x * WARPS_PER_CTA + w; row < B; row += warps_total)
    {
        const float* __restrict__ zr = z + (long long)row * 8192;

        // ---- phase 1: keys (strided 32B sectors; stay hot in L2) ----
        unsigned long long it[V];
        #pragma unroll
        for (int v = 0; v < V; ++v) {
            int i = lane * V + v;                   // blocked item assignment
            uint32_t kb = __float_as_uint(__ldg(zr + i * 16));
            kb = (kb & 0x80000000u) ? ~kb : (kb | 0x80000000u);   // monotone
            it[v] = ((unsigned long long)kb << 32) | (unsigned)i;
        }

        // ---- phase 2: bitonic sort, 512 items, registers + shfl ----
        #pragma unroll
        for (int k = 2; k <= V; k <<= 1) {
            #pragma unroll
            for (int j = k >> 1; j >= 1; j >>= 1) {
                #pragma unroll
                for (int v = 0; v < V; ++v) {
                    if ((v & j) == 0) {
                        int i = lane * V + v;
                        bool up = ((i & k) == 0);
                        ce(it[v], it[v | j], up);
                    }
                }
            }
        }
        #pragma unroll
        for (int k = 32; k <= 512; k <<= 1) {
            const bool up = ((lane & (k >> 4)) == 0);
            #pragma unroll
            for (int j = k >> 1; j >= V; j >>= 1) {
                const int  dl      = j >> 4;
                const bool keepmin = (((lane & dl) == 0) == up);
                #pragma unroll
                for (int v = 0; v < V; ++v) {
                    unsigned long long other = __shfl_xor_sync(0xFFFFFFFFu, it[v], dl);
                    if ((other < it[v]) == keepmin) it[v] = other;
                }
            }
            #pragma unroll
            for (int j = V >> 1; j >= 1; j >>= 1) {
                #pragma unroll
                for (int v = 0; v < V; ++v)
                    if ((v & j) == 0) ce(it[v], it[v | j], up);
            }
        }

        // ---- publish permutation (pairs packed into u32 stores) ----
        uint32_t* perm32 = (uint32_t*)sperm[w];
        #pragma unroll
        for (int v = 0; v < V; v += 2) {
            uint32_t lo = (uint32_t)(it[v]     & 0x1FFu);
            uint32_t hi = (uint32_t)(it[v + 1] & 0x1FFu);
            perm32[(lane * V + v) >> 1] = lo | (hi << 16);
        }
        __syncwarp();

        // ---- phase 3: gather global->global, batched for MLP ----
        const float4* __restrict__ in4  = (const float4*)zr;
        float4* __restrict__       out4 = (float4*)(out + (long long)row * 8192);
        const uint16_t* p = sperm[w];

        #pragma unroll 1
        for (int blk = 0; blk < 64; blk += 8) {
            float4 v4[8];
            #pragma unroll
            for (int u = 0; u < 8; ++u) {
                int f   = (blk + u) * 32 + lane;
                int src = p[f >> 2];
                v4[u] = __ldlu(&in4[src * 4 + (f & 3)]);   // last-use read
            }
            #pragma unroll
            for (int u = 0; u < 8; ++u) {
                int f = (blk + u) * 32 + lane;
                __stcs(&out4[f], v4[u]);                    // streaming write
            }
        }
        __syncwarp();
    }
}

extern "C" void kernel_launch(void* const* d_in, const int* in_sizes, int n_in,
                              void* d_out, int out_size)
{
    const float* z = (const float*)d_in[0];
    float* out     = (float*)d_out;
    const int D = 8192;                  // 512 packets * 16 floats
    int B = in_sizes[0] / D;             // 4096

    int grid = 148 * CTAS_PER_SM;        // persistent: 5 CTAs/SM, 20 warps/SM
    int max_grid = (B + WARPS_PER_CTA - 1) / WARPS_PER_CTA;
    if (grid > max_grid) grid = max_grid;
    sort_latent_kernel<<<grid, THREADS>>>(z, out, B);
}